// round 13
// baseline (speedup 1.0000x reference)
#include <cuda_runtime.h>
#include <cuda_bf16.h>
#include <cstdint>
#include <cstddef>

// Problem constants
#define BATCH 2
#define NPTS  40000
#define KNN   16
#define CIN   64
#define CADD  3
#define CTOT  67
#define MDIM  16
#define FDIM  1072            // CTOT*MDIM
#define FDIMP 1088            // padded: 34 chunks of 32 bf16
#define ROWB  2176            // FDIMP * 2 bytes
#define COUT  128
#define TOTPTS (BATCH * NPTS) // 80000

// GEMM tiling — XOR-swizzled 64B rows, 3 stages, 2 blocks/SM (R12, frozen)
#define BK      32
#define NCH     34            // FDIMP / BK
#define NSTG    3
#define TILE_SB (128 * 64)           // 8192 B per operand tile (no padding)
#define STAGE_SB (4 * TILE_SB)       // Ah, Al, Bh, Bl = 32768 B
#define SMEM_DYN (NSTG * STAGE_SB)   // 98304 B -> 2 blocks/SM

// ---------------------------------------------------------------------------
// Device-global scratch (no runtime allocation allowed)
// ---------------------------------------------------------------------------
__device__ __nv_bfloat16 g_Ph[(size_t)TOTPTS * FDIMP];  // 174 MB
__device__ __nv_bfloat16 g_Pl[(size_t)TOTPTS * FDIMP];  // 174 MB
__device__ __nv_bfloat16 g_Wh[COUT * FDIMP];
__device__ __nv_bfloat16 g_Wl[COUT * FDIMP];
__device__ int g_is64;

// ---------------------------------------------------------------------------
// PTX helpers (base sm_103 target — tcgen05 is NOT available, per R3)
// ---------------------------------------------------------------------------
__device__ __forceinline__ uint32_t smem_u32(const void* p) {
    uint32_t a;
    asm("{ .reg .u64 t; cvta.to.shared.u64 t, %1; cvt.u32.u64 %0, t; }" : "=r"(a) : "l"(p));
    return a;
}
__device__ __forceinline__ void cpasync16(uint32_t dst, const void* src) {
    asm volatile("cp.async.cg.shared.global [%0], [%1], 16;" :: "r"(dst), "l"(src));
}
#define CP_COMMIT() asm volatile("cp.async.commit_group;" ::: "memory")
#define CP_WAIT2()  asm volatile("cp.async.wait_group 2;" ::: "memory")

__device__ __forceinline__ void ldsm4(uint32_t* r, uint32_t addr) {
    asm volatile("ldmatrix.sync.aligned.m8n8.x4.shared.b16 {%0,%1,%2,%3}, [%4];"
                 : "=r"(r[0]), "=r"(r[1]), "=r"(r[2]), "=r"(r[3]) : "r"(addr));
}
__device__ __forceinline__ void mma_bf16(float* d, const uint32_t* a, const uint32_t* b) {
    asm volatile("mma.sync.aligned.m16n8k16.row.col.f32.bf16.bf16.f32 "
                 "{%0,%1,%2,%3}, {%4,%5,%6,%7}, {%8,%9}, {%0,%1,%2,%3};"
                 : "+f"(d[0]), "+f"(d[1]), "+f"(d[2]), "+f"(d[3])
                 : "r"(a[0]), "r"(a[1]), "r"(a[2]), "r"(a[3]), "r"(b[0]), "r"(b[1]));
}

// XOR swizzle for 64B rows: logical 16B chunk c -> physical c ^ ((row>>1)&3).
__device__ __forceinline__ uint32_t sw_off(uint32_t row, uint32_t c) {
    return row * 64 + ((c ^ ((row >> 1) & 3)) << 4);
}

// ---------------------------------------------------------------------------
// Index dtype detection (i64 vs i32 neighbor_inds)
// ---------------------------------------------------------------------------
__global__ void detect_kernel(const void* __restrict__ idx) {
    const unsigned* p = (const unsigned*)idx;
    int is64 = 1;
    for (int i = 0; i < 64; ++i)
        if (p[2 * i + 1] != 0u) { is64 = 0; break; }
    g_is64 = is64;
}

// ---------------------------------------------------------------------------
// Weight split: W[128,1072] fp32 -> Wh/Wl [128,1088] bf16 (zero padded)
// ---------------------------------------------------------------------------
__global__ void wconv_kernel(const float* __restrict__ W) {
    int i = blockIdx.x * blockDim.x + threadIdx.x;
    if (i >= COUT * FDIMP) return;
    int row = i / FDIMP, col = i - row * FDIMP;
    float v = (col < FDIM) ? W[row * FDIM + col] : 0.f;
    __nv_bfloat16 h = __float2bfloat16(v);
    g_Wh[i] = h;
    g_Wl[i] = __float2bfloat16(v - __bfloat162float(h));
}

// ---------------------------------------------------------------------------
// Kernel 1: per-point PConv -> bf16 hi/lo split.
// R13: thread = (channel, m-half); all 128 lanes active in compute phase.
// Same k-accumulation order per (c,m) as R11 -> bit-identical results.
// ---------------------------------------------------------------------------
__device__ __forceinline__ void emit_half(int point, int c, int h, const float* acc) {
    unsigned hh[4], ll[4];
    #pragma unroll
    for (int m = 0; m < 8; m += 2) {
        __nv_bfloat16 h0 = __float2bfloat16(acc[m]);
        __nv_bfloat16 h1 = __float2bfloat16(acc[m + 1]);
        __nv_bfloat16 l0 = __float2bfloat16(acc[m] - __bfloat162float(h0));
        __nv_bfloat16 l1 = __float2bfloat16(acc[m + 1] - __bfloat162float(h1));
        hh[m >> 1] = (unsigned)__bfloat16_as_ushort(h0) | ((unsigned)__bfloat16_as_ushort(h1) << 16);
        ll[m >> 1] = (unsigned)__bfloat16_as_ushort(l0) | ((unsigned)__bfloat16_as_ushort(l1) << 16);
    }
    const size_t off = (size_t)point * FDIMP + c * 16 + h * 8;
    *(uint4*)(g_Ph + off) = make_uint4(hh[0], hh[1], hh[2], hh[3]);
    *(uint4*)(g_Pl + off) = make_uint4(ll[0], ll[1], ll[2], ll[3]);
}

__global__ void __launch_bounds__(128, 16) pconv_kernel(
    const float* __restrict__ in_feat,
    const void*  __restrict__ idx,       // neighbor_inds, i64 or i32
    const float* __restrict__ wn,
    const float* __restrict__ addf)
{
    __shared__ float feats[KNN][68];
    __shared__ float wns[KNN][MDIM];
    __shared__ int   nb[KNN];

    const int point = blockIdx.x;
    const int b     = point / NPTS;
    const int tid   = threadIdx.x;

    if (tid < KNN) {
        int v;
        if (g_is64) v = (int)((const long long*)idx)[(size_t)point * KNN + tid];
        else        v = ((const int*)idx)[(size_t)point * KNN + tid];
        nb[tid] = v;
    }
    if (tid < 64) {
        float4 w = ((const float4*)wn)[(size_t)point * 64 + tid];
        ((float4*)&wns[0][0])[tid] = w;
    }
    if (tid < KNN * CADD) {
        int k = tid / CADD, a = tid - k * CADD;
        feats[k][CIN + a] = addf[(size_t)point * (KNN * CADD) + tid];
    }
    __syncthreads();

    #pragma unroll
    for (int i = tid; i < KNN * 16; i += 128) {
        int k = i >> 4, q = i & 15;
        float4 v = ((const float4*)in_feat)[((size_t)b * NPTS + nb[k]) * 16 + q];
        *((float4*)&feats[k][q * 4]) = v;
    }
    __syncthreads();

    const int c = tid >> 1;       // channel 0..63
    const int h = tid & 1;        // m-half: m in [h*8, h*8+8)

    {   // main pass: all 128 threads active
        float acc[8];
        #pragma unroll
        for (int m = 0; m < 8; ++m) acc[m] = 0.f;
        #pragma unroll
        for (int k = 0; k < KNN; ++k) {
            float f = feats[k][c];
            const float4* wr = (const float4*)&wns[k][0];
            float4 w0 = wr[h * 2], w1 = wr[h * 2 + 1];
            acc[0] += f * w0.x; acc[1] += f * w0.y; acc[2] += f * w0.z; acc[3] += f * w0.w;
            acc[4] += f * w1.x; acc[5] += f * w1.y; acc[6] += f * w1.z; acc[7] += f * w1.w;
        }
        emit_half(point, c, h, acc);
    }

    if (tid < 8) {   // tail: channels 64..66 (addf) and 67 (zero pad)
        const int c2 = 64 + (tid >> 1);
        float acc[8];
        #pragma unroll
        for (int m = 0; m < 8; ++m) acc[m] = 0.f;
        if (c2 < CTOT) {
            #pragma unroll
            for (int k = 0; k < KNN; ++k) {
                float f = feats[k][c2];
                const float4* wr = (const float4*)&wns[k][0];
                float4 w0 = wr[h * 2], w1 = wr[h * 2 + 1];
                acc[0] += f * w0.x; acc[1] += f * w0.y; acc[2] += f * w0.z; acc[3] += f * w0.w;
                acc[4] += f * w1.x; acc[5] += f * w1.y; acc[6] += f * w1.z; acc[7] += f * w1.w;
            }
        }
        emit_half(point, c2, h, acc);
    }
}

// ---------------------------------------------------------------------------
// Kernel 2: mma.sync bf16-split GEMM (R12 config, frozen).
// 625 blocks x (M=128, N=128), BK=32, 256 threads (8 warps, warp tile 32x64),
// 3-stage cp.async pipeline + XOR-swizzled 64B rows, 2 blocks/SM.
// Split-3: AhBh + AhBl + AlBh.
// ---------------------------------------------------------------------------
__global__ void __launch_bounds__(256, 2)
gemm_mma_kernel(const float* __restrict__ bias, float* __restrict__ out)
{
    extern __shared__ char dsm[];
    __shared__ float bias_s[COUT];

    const int tid  = threadIdx.x;
    const int lane = tid & 31;
    const int wid  = tid >> 5;
    const int wm   = wid & 3;            // 4 warps along M (32 rows each)
    const int wn   = wid >> 2;           // 2 warps along N (64 cols each)
    const size_t rowBase = (size_t)blockIdx.x * 128;
    const uint32_t tb = smem_u32(dsm);

    if (tid < COUT) bias_s[tid] = bias[tid];

    const char* srcs[4] = {
        (const char*)g_Ph + rowBase * ROWB,
        (const char*)g_Pl + rowBase * ROWB,
        (const char*)g_Wh,
        (const char*)g_Wl
    };

    auto load_chunk = [&](int chunk, int s) {
        const uint32_t st = tb + s * STAGE_SB;
        const size_t coff = (size_t)chunk * (BK * 2);   // 64 B along K
        #pragma unroll
        for (int i = 0; i < 8; ++i) {
            int j = tid + i * 256;          // 0..2047
            int tile = j >> 9;              // 0..3
            int idx  = j & 511;
            int row  = idx >> 2;            // 0..127
            int c    = idx & 3;             // logical 16B chunk in 64B row
            cpasync16(st + tile * TILE_SB + sw_off(row, c),
                      srcs[tile] + (size_t)row * ROWB + coff + c * 16);
        }
    };

    float acc[2][8][4];
    #pragma unroll
    for (int mt = 0; mt < 2; ++mt)
        #pragma unroll
        for (int nt = 0; nt < 8; ++nt)
            #pragma unroll
            for (int r = 0; r < 4; ++r) acc[mt][nt][r] = 0.f;

    const uint32_t a_row0 = (uint32_t)(wm * 32 + (lane & 15));
    const uint32_t a_c0   = (uint32_t)(lane >> 4);            // + k16*2
    const uint32_t b_row0 = (uint32_t)(wn * 64 + ((lane >> 4) << 3) + (lane & 7));
    const uint32_t b_c0   = (uint32_t)((lane >> 3) & 1);      // + k16*2

    load_chunk(0, 0); CP_COMMIT();
    load_chunk(1, 1); CP_COMMIT();

    for (int t = 0; t < NCH; ++t) {
        const int s = t % NSTG;
        if (t + 2 < NCH) load_chunk(t + 2, (t + 2) % NSTG);
        CP_COMMIT();          // one group per iteration (may be empty at tail)
        CP_WAIT2();           // chunk t resident
        __syncthreads();

        const uint32_t st = tb + s * STAGE_SB;

        #pragma unroll
        for (int k16 = 0; k16 < 2; ++k16) {
            uint32_t a_h[2][4], a_l[2][4], b_h[8][2], b_l[8][2];
            #pragma unroll
            for (int mt = 0; mt < 2; ++mt) {
                const uint32_t off = sw_off(a_row0 + mt * 16, a_c0 + k16 * 2);
                ldsm4(a_h[mt], st + off);
                ldsm4(a_l[mt], st + TILE_SB + off);
            }
            #pragma unroll
            for (int nt2 = 0; nt2 < 4; ++nt2) {
                const uint32_t off = sw_off(b_row0 + nt2 * 16, b_c0 + k16 * 2);
                uint32_t r[4];
                ldsm4(r, st + 2 * TILE_SB + off);
                b_h[nt2 * 2][0] = r[0]; b_h[nt2 * 2][1] = r[1];
                b_h[nt2 * 2 + 1][0] = r[2]; b_h[nt2 * 2 + 1][1] = r[3];
                ldsm4(r, st + 3 * TILE_SB + off);
                b_l[nt2 * 2][0] = r[0]; b_l[nt2 * 2][1] = r[1];
                b_l[nt2 * 2 + 1][0] = r[2]; b_l[nt2 * 2 + 1][1] = r[3];
            }
            #pragma unroll
            for (int mt = 0; mt < 2; ++mt)
                #pragma unroll
                for (int nt = 0; nt < 8; ++nt) {
                    mma_bf16(acc[mt][nt], a_h[mt], b_h[nt]);
                    mma_bf16(acc[mt][nt], a_h[mt], b_l[nt]);
                    mma_bf16(acc[mt][nt], a_l[mt], b_h[nt]);
                }
        }
        __syncthreads();
    }

    // epilogue: bias + store (float2 per fragment half-row)
    #pragma unroll
    for (int mt = 0; mt < 2; ++mt) {
        const size_t r0 = rowBase + (size_t)(wm * 32 + mt * 16 + (lane >> 2));
        #pragma unroll
        for (int nt = 0; nt < 8; ++nt) {
            const int col = wn * 64 + nt * 8 + (lane & 3) * 2;
            const float b0 = bias_s[col], b1 = bias_s[col + 1];
            *(float2*)(out + r0 * COUT + col) =
                make_float2(acc[mt][nt][0] + b0, acc[mt][nt][1] + b1);
            *(float2*)(out + (r0 + 8) * COUT + col) =
                make_float2(acc[mt][nt][2] + b0, acc[mt][nt][3] + b1);
        }
    }
}

// ---------------------------------------------------------------------------
// Launch
// ---------------------------------------------------------------------------
extern "C" void kernel_launch(void* const* d_in, const int* in_sizes, int n_in,
                              void* d_out, int out_size)
{
    const float* in_feat = (const float*)d_in[0];
    const void*  ninds   = d_in[1];
    const float* wn      = (const float*)d_in[5];
    const float* addf    = (const float*)d_in[6];
    const float* W       = (const float*)d_in[7];
    const float* bias    = (const float*)d_in[8];
    float*       out     = (float*)d_out;

    cudaFuncSetAttribute(gemm_mma_kernel,
                         cudaFuncAttributeMaxDynamicSharedMemorySize, SMEM_DYN);

    detect_kernel<<<1, 1>>>(ninds);
    wconv_kernel<<<(COUT * FDIMP + 255) / 256, 256>>>(W);
    pconv_kernel<<<TOTPTS, 128>>>(in_feat, ninds, wn, addf);
    gemm_mma_kernel<<<TOTPTS / 128, 256, SMEM_DYN>>>(bias, out);
}

// round 14
// speedup vs baseline: 1.2792x; 1.2792x over previous
#include <cuda_runtime.h>
#include <cuda_bf16.h>
#include <cstdint>
#include <cstddef>

// Problem constants
#define BATCH 2
#define NPTS  40000
#define KNN   16
#define CIN   64
#define CADD  3
#define CTOT  67
#define MDIM  16
#define FDIM  1072            // CTOT*MDIM
#define FDIMP 1088            // padded: 34 chunks of 32 bf16
#define ROWB  2176            // FDIMP * 2 bytes
#define COUT  128
#define TOTPTS (BATCH * NPTS) // 80000

// GEMM tiling — XOR-swizzled 64B rows, 3 stages, 2 blocks/SM (R12, frozen)
#define BK      32
#define NCH     34            // FDIMP / BK
#define NSTG    3
#define TILE_SB (128 * 64)           // 8192 B per operand tile (no padding)
#define STAGE_SB (4 * TILE_SB)       // Ah, Al, Bh, Bl = 32768 B
#define SMEM_DYN (NSTG * STAGE_SB)   // 98304 B -> 2 blocks/SM

// ---------------------------------------------------------------------------
// Device-global scratch (no runtime allocation allowed)
// ---------------------------------------------------------------------------
__device__ __nv_bfloat16 g_Ph[(size_t)TOTPTS * FDIMP];  // 174 MB
__device__ __nv_bfloat16 g_Pl[(size_t)TOTPTS * FDIMP];  // 174 MB
__device__ __nv_bfloat16 g_Wh[COUT * FDIMP];
__device__ __nv_bfloat16 g_Wl[COUT * FDIMP];
__device__ int g_is64;

// ---------------------------------------------------------------------------
// PTX helpers (base sm_103 target — tcgen05 is NOT available, per R3)
// ---------------------------------------------------------------------------
__device__ __forceinline__ uint32_t smem_u32(const void* p) {
    uint32_t a;
    asm("{ .reg .u64 t; cvta.to.shared.u64 t, %1; cvt.u32.u64 %0, t; }" : "=r"(a) : "l"(p));
    return a;
}
__device__ __forceinline__ void cpasync16(uint32_t dst, const void* src) {
    asm volatile("cp.async.cg.shared.global [%0], [%1], 16;" :: "r"(dst), "l"(src));
}
#define CP_COMMIT() asm volatile("cp.async.commit_group;" ::: "memory")
#define CP_WAIT2()  asm volatile("cp.async.wait_group 2;" ::: "memory")

__device__ __forceinline__ void ldsm4(uint32_t* r, uint32_t addr) {
    asm volatile("ldmatrix.sync.aligned.m8n8.x4.shared.b16 {%0,%1,%2,%3}, [%4];"
                 : "=r"(r[0]), "=r"(r[1]), "=r"(r[2]), "=r"(r[3]) : "r"(addr));
}
__device__ __forceinline__ void mma_bf16(float* d, const uint32_t* a, const uint32_t* b) {
    asm volatile("mma.sync.aligned.m16n8k16.row.col.f32.bf16.bf16.f32 "
                 "{%0,%1,%2,%3}, {%4,%5,%6,%7}, {%8,%9}, {%0,%1,%2,%3};"
                 : "+f"(d[0]), "+f"(d[1]), "+f"(d[2]), "+f"(d[3])
                 : "r"(a[0]), "r"(a[1]), "r"(a[2]), "r"(a[3]), "r"(b[0]), "r"(b[1]));
}

// XOR swizzle for 64B rows: logical 16B chunk c -> physical c ^ ((row>>1)&3).
__device__ __forceinline__ uint32_t sw_off(uint32_t row, uint32_t c) {
    return row * 64 + ((c ^ ((row >> 1) & 3)) << 4);
}

// ---------------------------------------------------------------------------
// Index dtype detection (i64 vs i32 neighbor_inds)
// ---------------------------------------------------------------------------
__global__ void detect_kernel(const void* __restrict__ idx) {
    const unsigned* p = (const unsigned*)idx;
    int is64 = 1;
    for (int i = 0; i < 64; ++i)
        if (p[2 * i + 1] != 0u) { is64 = 0; break; }
    g_is64 = is64;
}

// ---------------------------------------------------------------------------
// Weight split: W[128,1072] fp32 -> Wh/Wl [128,1088] bf16 (zero padded)
// ---------------------------------------------------------------------------
__global__ void wconv_kernel(const float* __restrict__ W) {
    int i = blockIdx.x * blockDim.x + threadIdx.x;
    if (i >= COUT * FDIMP) return;
    int row = i / FDIMP, col = i - row * FDIMP;
    float v = (col < FDIM) ? W[row * FDIM + col] : 0.f;
    __nv_bfloat16 h = __float2bfloat16(v);
    g_Wh[i] = h;
    g_Wl[i] = __float2bfloat16(v - __bfloat162float(h));
}

// ---------------------------------------------------------------------------
// Kernel 1: per-point PConv -> bf16 hi/lo split.
// Thread = (channel, m-half); all 128 lanes active in compute phase.
// R14: minBlocks 16 -> 12 (reg cap 42, no spills — R13's cap of 32 spilled
// the accumulators to local memory, 10x regression).
// Same k-accumulation order per (c,m) as R11 -> bit-identical results.
// ---------------------------------------------------------------------------
__device__ __forceinline__ void emit_half(int point, int c, int h, const float* acc) {
    unsigned hh[4], ll[4];
    #pragma unroll
    for (int m = 0; m < 8; m += 2) {
        __nv_bfloat16 h0 = __float2bfloat16(acc[m]);
        __nv_bfloat16 h1 = __float2bfloat16(acc[m + 1]);
        __nv_bfloat16 l0 = __float2bfloat16(acc[m] - __bfloat162float(h0));
        __nv_bfloat16 l1 = __float2bfloat16(acc[m + 1] - __bfloat162float(h1));
        hh[m >> 1] = (unsigned)__bfloat16_as_ushort(h0) | ((unsigned)__bfloat16_as_ushort(h1) << 16);
        ll[m >> 1] = (unsigned)__bfloat16_as_ushort(l0) | ((unsigned)__bfloat16_as_ushort(l1) << 16);
    }
    const size_t off = (size_t)point * FDIMP + c * 16 + h * 8;
    *(uint4*)(g_Ph + off) = make_uint4(hh[0], hh[1], hh[2], hh[3]);
    *(uint4*)(g_Pl + off) = make_uint4(ll[0], ll[1], ll[2], ll[3]);
}

__global__ void __launch_bounds__(128, 12) pconv_kernel(
    const float* __restrict__ in_feat,
    const void*  __restrict__ idx,       // neighbor_inds, i64 or i32
    const float* __restrict__ wn,
    const float* __restrict__ addf)
{
    __shared__ float feats[KNN][68];
    __shared__ float wns[KNN][MDIM];
    __shared__ int   nb[KNN];

    const int point = blockIdx.x;
    const int b     = point / NPTS;
    const int tid   = threadIdx.x;

    if (tid < KNN) {
        int v;
        if (g_is64) v = (int)((const long long*)idx)[(size_t)point * KNN + tid];
        else        v = ((const int*)idx)[(size_t)point * KNN + tid];
        nb[tid] = v;
    }
    if (tid < 64) {
        float4 w = ((const float4*)wn)[(size_t)point * 64 + tid];
        ((float4*)&wns[0][0])[tid] = w;
    }
    if (tid < KNN * CADD) {
        int k = tid / CADD, a = tid - k * CADD;
        feats[k][CIN + a] = addf[(size_t)point * (KNN * CADD) + tid];
    }
    __syncthreads();

    #pragma unroll
    for (int i = tid; i < KNN * 16; i += 128) {
        int k = i >> 4, q = i & 15;
        float4 v = ((const float4*)in_feat)[((size_t)b * NPTS + nb[k]) * 16 + q];
        *((float4*)&feats[k][q * 4]) = v;
    }
    __syncthreads();

    const int c = tid >> 1;       // channel 0..63
    const int h = tid & 1;        // m-half: m in [h*8, h*8+8)

    {   // main pass: all 128 threads active
        float acc[8];
        #pragma unroll
        for (int m = 0; m < 8; ++m) acc[m] = 0.f;
        #pragma unroll
        for (int k = 0; k < KNN; ++k) {
            float f = feats[k][c];
            const float4* wr = (const float4*)&wns[k][0];
            float4 w0 = wr[h * 2], w1 = wr[h * 2 + 1];
            acc[0] += f * w0.x; acc[1] += f * w0.y; acc[2] += f * w0.z; acc[3] += f * w0.w;
            acc[4] += f * w1.x; acc[5] += f * w1.y; acc[6] += f * w1.z; acc[7] += f * w1.w;
        }
        emit_half(point, c, h, acc);
    }

    if (tid < 8) {   // tail: channels 64..66 (addf) and 67 (zero pad)
        const int c2 = 64 + (tid >> 1);
        float acc[8];
        #pragma unroll
        for (int m = 0; m < 8; ++m) acc[m] = 0.f;
        if (c2 < CTOT) {
            #pragma unroll
            for (int k = 0; k < KNN; ++k) {
                float f = feats[k][c2];
                const float4* wr = (const float4*)&wns[k][0];
                float4 w0 = wr[h * 2], w1 = wr[h * 2 + 1];
                acc[0] += f * w0.x; acc[1] += f * w0.y; acc[2] += f * w0.z; acc[3] += f * w0.w;
                acc[4] += f * w1.x; acc[5] += f * w1.y; acc[6] += f * w1.z; acc[7] += f * w1.w;
            }
        }
        emit_half(point, c2, h, acc);
    }
}

// ---------------------------------------------------------------------------
// Kernel 2: mma.sync bf16-split GEMM (R12 config, frozen).
// 625 blocks x (M=128, N=128), BK=32, 256 threads (8 warps, warp tile 32x64),
// 3-stage cp.async pipeline + XOR-swizzled 64B rows, 2 blocks/SM.
// Split-3: AhBh + AhBl + AlBh.
// ---------------------------------------------------------------------------
__global__ void __launch_bounds__(256, 2)
gemm_mma_kernel(const float* __restrict__ bias, float* __restrict__ out)
{
    extern __shared__ char dsm[];
    __shared__ float bias_s[COUT];

    const int tid  = threadIdx.x;
    const int lane = tid & 31;
    const int wid  = tid >> 5;
    const int wm   = wid & 3;            // 4 warps along M (32 rows each)
    const int wn   = wid >> 2;           // 2 warps along N (64 cols each)
    const size_t rowBase = (size_t)blockIdx.x * 128;
    const uint32_t tb = smem_u32(dsm);

    if (tid < COUT) bias_s[tid] = bias[tid];

    const char* srcs[4] = {
        (const char*)g_Ph + rowBase * ROWB,
        (const char*)g_Pl + rowBase * ROWB,
        (const char*)g_Wh,
        (const char*)g_Wl
    };

    auto load_chunk = [&](int chunk, int s) {
        const uint32_t st = tb + s * STAGE_SB;
        const size_t coff = (size_t)chunk * (BK * 2);   // 64 B along K
        #pragma unroll
        for (int i = 0; i < 8; ++i) {
            int j = tid + i * 256;          // 0..2047
            int tile = j >> 9;              // 0..3
            int idx  = j & 511;
            int row  = idx >> 2;            // 0..127
            int c    = idx & 3;             // logical 16B chunk in 64B row
            cpasync16(st + tile * TILE_SB + sw_off(row, c),
                      srcs[tile] + (size_t)row * ROWB + coff + c * 16);
        }
    };

    float acc[2][8][4];
    #pragma unroll
    for (int mt = 0; mt < 2; ++mt)
        #pragma unroll
        for (int nt = 0; nt < 8; ++nt)
            #pragma unroll
            for (int r = 0; r < 4; ++r) acc[mt][nt][r] = 0.f;

    const uint32_t a_row0 = (uint32_t)(wm * 32 + (lane & 15));
    const uint32_t a_c0   = (uint32_t)(lane >> 4);            // + k16*2
    const uint32_t b_row0 = (uint32_t)(wn * 64 + ((lane >> 4) << 3) + (lane & 7));
    const uint32_t b_c0   = (uint32_t)((lane >> 3) & 1);      // + k16*2

    load_chunk(0, 0); CP_COMMIT();
    load_chunk(1, 1); CP_COMMIT();

    for (int t = 0; t < NCH; ++t) {
        const int s = t % NSTG;
        if (t + 2 < NCH) load_chunk(t + 2, (t + 2) % NSTG);
        CP_COMMIT();          // one group per iteration (may be empty at tail)
        CP_WAIT2();           // chunk t resident
        __syncthreads();

        const uint32_t st = tb + s * STAGE_SB;

        #pragma unroll
        for (int k16 = 0; k16 < 2; ++k16) {
            uint32_t a_h[2][4], a_l[2][4], b_h[8][2], b_l[8][2];
            #pragma unroll
            for (int mt = 0; mt < 2; ++mt) {
                const uint32_t off = sw_off(a_row0 + mt * 16, a_c0 + k16 * 2);
                ldsm4(a_h[mt], st + off);
                ldsm4(a_l[mt], st + TILE_SB + off);
            }
            #pragma unroll
            for (int nt2 = 0; nt2 < 4; ++nt2) {
                const uint32_t off = sw_off(b_row0 + nt2 * 16, b_c0 + k16 * 2);
                uint32_t r[4];
                ldsm4(r, st + 2 * TILE_SB + off);
                b_h[nt2 * 2][0] = r[0]; b_h[nt2 * 2][1] = r[1];
                b_h[nt2 * 2 + 1][0] = r[2]; b_h[nt2 * 2 + 1][1] = r[3];
                ldsm4(r, st + 3 * TILE_SB + off);
                b_l[nt2 * 2][0] = r[0]; b_l[nt2 * 2][1] = r[1];
                b_l[nt2 * 2 + 1][0] = r[2]; b_l[nt2 * 2 + 1][1] = r[3];
            }
            #pragma unroll
            for (int mt = 0; mt < 2; ++mt)
                #pragma unroll
                for (int nt = 0; nt < 8; ++nt) {
                    mma_bf16(acc[mt][nt], a_h[mt], b_h[nt]);
                    mma_bf16(acc[mt][nt], a_h[mt], b_l[nt]);
                    mma_bf16(acc[mt][nt], a_l[mt], b_h[nt]);
                }
        }
        __syncthreads();
    }

    // epilogue: bias + store (float2 per fragment half-row)
    #pragma unroll
    for (int mt = 0; mt < 2; ++mt) {
        const size_t r0 = rowBase + (size_t)(wm * 32 + mt * 16 + (lane >> 2));
        #pragma unroll
        for (int nt = 0; nt < 8; ++nt) {
            const int col = wn * 64 + nt * 8 + (lane & 3) * 2;
            const float b0 = bias_s[col], b1 = bias_s[col + 1];
            *(float2*)(out + r0 * COUT + col) =
                make_float2(acc[mt][nt][0] + b0, acc[mt][nt][1] + b1);
            *(float2*)(out + (r0 + 8) * COUT + col) =
                make_float2(acc[mt][nt][2] + b0, acc[mt][nt][3] + b1);
        }
    }
}

// ---------------------------------------------------------------------------
// Launch
// ---------------------------------------------------------------------------
extern "C" void kernel_launch(void* const* d_in, const int* in_sizes, int n_in,
                              void* d_out, int out_size)
{
    const float* in_feat = (const float*)d_in[0];
    const void*  ninds   = d_in[1];
    const float* wn      = (const float*)d_in[5];
    const float* addf    = (const float*)d_in[6];
    const float* W       = (const float*)d_in[7];
    const float* bias    = (const float*)d_in[8];
    float*       out     = (float*)d_out;

    cudaFuncSetAttribute(gemm_mma_kernel,
                         cudaFuncAttributeMaxDynamicSharedMemorySize, SMEM_DYN);

    detect_kernel<<<1, 1>>>(ninds);
    wconv_kernel<<<(COUT * FDIMP + 255) / 256, 256>>>(W);
    pconv_kernel<<<TOTPTS, 128>>>(in_feat, ninds, wn, addf);
    gemm_mma_kernel<<<TOTPTS / 128, 256, SMEM_DYN>>>(bias, out);
}

// round 15
// speedup vs baseline: 4.9829x; 3.8952x over previous
#include <cuda_runtime.h>
#include <cuda_bf16.h>
#include <cstdint>
#include <cstddef>

// Problem constants
#define BATCH 2
#define NPTS  40000
#define KNN   16
#define CIN   64
#define CADD  3
#define CTOT  67
#define MDIM  16
#define FDIM  1072            // CTOT*MDIM
#define FDIMP 1088            // padded: 34 chunks of 32 bf16
#define ROWB  2176            // FDIMP * 2 bytes
#define COUT  128
#define TOTPTS (BATCH * NPTS) // 80000

// GEMM tiling — XOR-swizzled 64B rows, 3 stages, 2 blocks/SM (R12, frozen)
#define BK      32
#define NCH     34            // FDIMP / BK
#define NSTG    3
#define TILE_SB (128 * 64)           // 8192 B per operand tile (no padding)
#define STAGE_SB (4 * TILE_SB)       // Ah, Al, Bh, Bl = 32768 B
#define SMEM_DYN (NSTG * STAGE_SB)   // 98304 B -> 2 blocks/SM

// ---------------------------------------------------------------------------
// Device-global scratch (no runtime allocation allowed)
// ---------------------------------------------------------------------------
__device__ __nv_bfloat16 g_Ph[(size_t)TOTPTS * FDIMP];  // 174 MB
__device__ __nv_bfloat16 g_Pl[(size_t)TOTPTS * FDIMP];  // 174 MB
__device__ __nv_bfloat16 g_Wh[COUT * FDIMP];
__device__ __nv_bfloat16 g_Wl[COUT * FDIMP];
__device__ int g_is64;

// ---------------------------------------------------------------------------
// PTX helpers (base sm_103 target — tcgen05 is NOT available, per R3)
// ---------------------------------------------------------------------------
__device__ __forceinline__ uint32_t smem_u32(const void* p) {
    uint32_t a;
    asm("{ .reg .u64 t; cvta.to.shared.u64 t, %1; cvt.u32.u64 %0, t; }" : "=r"(a) : "l"(p));
    return a;
}
__device__ __forceinline__ void cpasync16(uint32_t dst, const void* src) {
    asm volatile("cp.async.cg.shared.global [%0], [%1], 16;" :: "r"(dst), "l"(src));
}
#define CP_COMMIT() asm volatile("cp.async.commit_group;" ::: "memory")
#define CP_WAIT2()  asm volatile("cp.async.wait_group 2;" ::: "memory")

__device__ __forceinline__ void ldsm4(uint32_t* r, uint32_t addr) {
    asm volatile("ldmatrix.sync.aligned.m8n8.x4.shared.b16 {%0,%1,%2,%3}, [%4];"
                 : "=r"(r[0]), "=r"(r[1]), "=r"(r[2]), "=r"(r[3]) : "r"(addr));
}
__device__ __forceinline__ void mma_bf16(float* d, const uint32_t* a, const uint32_t* b) {
    asm volatile("mma.sync.aligned.m16n8k16.row.col.f32.bf16.bf16.f32 "
                 "{%0,%1,%2,%3}, {%4,%5,%6,%7}, {%8,%9}, {%0,%1,%2,%3};"
                 : "+f"(d[0]), "+f"(d[1]), "+f"(d[2]), "+f"(d[3])
                 : "r"(a[0]), "r"(a[1]), "r"(a[2]), "r"(a[3]), "r"(b[0]), "r"(b[1]));
}

// XOR swizzle for 64B rows: logical 16B chunk c -> physical c ^ ((row>>1)&3).
__device__ __forceinline__ uint32_t sw_off(uint32_t row, uint32_t c) {
    return row * 64 + ((c ^ ((row >> 1) & 3)) << 4);
}

// Packed fp32 pair FMA: lanewise fma.rn — bit-identical to two scalar FFMAs.
__device__ __forceinline__ void fma_f32x2(unsigned long long& acc,
                                          unsigned long long w,
                                          unsigned long long f) {
    asm("fma.rn.f32x2 %0, %1, %2, %0;" : "+l"(acc) : "l"(w), "l"(f));
}

// ---------------------------------------------------------------------------
// Index dtype detection (i64 vs i32 neighbor_inds)
// ---------------------------------------------------------------------------
__global__ void detect_kernel(const void* __restrict__ idx) {
    const unsigned* p = (const unsigned*)idx;
    int is64 = 1;
    for (int i = 0; i < 64; ++i)
        if (p[2 * i + 1] != 0u) { is64 = 0; break; }
    g_is64 = is64;
}

// ---------------------------------------------------------------------------
// Weight split: W[128,1072] fp32 -> Wh/Wl [128,1088] bf16 (zero padded)
// ---------------------------------------------------------------------------
__global__ void wconv_kernel(const float* __restrict__ W) {
    int i = blockIdx.x * blockDim.x + threadIdx.x;
    if (i >= COUT * FDIMP) return;
    int row = i / FDIMP, col = i - row * FDIMP;
    float v = (col < FDIM) ? W[row * FDIM + col] : 0.f;
    __nv_bfloat16 h = __float2bfloat16(v);
    g_Wh[i] = h;
    g_Wl[i] = __float2bfloat16(v - __bfloat162float(h));
}

// ---------------------------------------------------------------------------
// Kernel 1: per-point PConv -> bf16 hi/lo split.
// R12 structure (thread = channel, 67 active); R15: inner accumulation via
// packed fma.rn.f32x2 (8 FFMA2 issues per k instead of 16 FFMA) with w-pairs
// loaded directly as ld.shared.v2.u64. Same per-(c,m) k-order -> bit-identical.
// ---------------------------------------------------------------------------
__global__ void __launch_bounds__(128, 12) pconv_kernel(
    const float* __restrict__ in_feat,
    const void*  __restrict__ idx,       // neighbor_inds, i64 or i32
    const float* __restrict__ wn,
    const float* __restrict__ addf)
{
    __shared__ float feats[KNN][68];
    __shared__ __align__(16) float wns[KNN][MDIM];
    __shared__ int nb[KNN];

    const int point = blockIdx.x;
    const int b     = point / NPTS;
    const int tid   = threadIdx.x;

    if (tid < KNN) {
        int v;
        if (g_is64) v = (int)((const long long*)idx)[(size_t)point * KNN + tid];
        else        v = ((const int*)idx)[(size_t)point * KNN + tid];
        nb[tid] = v;
    }
    if (tid < 64) {
        float4 w = ((const float4*)wn)[(size_t)point * 64 + tid];
        ((float4*)&wns[0][0])[tid] = w;
    }
    if (tid < KNN * CADD) {
        int k = tid / CADD, a = tid - k * CADD;
        feats[k][CIN + a] = addf[(size_t)point * (KNN * CADD) + tid];
    }
    __syncthreads();

    #pragma unroll
    for (int i = tid; i < KNN * 16; i += 128) {
        int k = i >> 4, q = i & 15;
        float4 v = ((const float4*)in_feat)[((size_t)b * NPTS + nb[k]) * 16 + q];
        *((float4*)&feats[k][q * 4]) = v;
    }
    __syncthreads();

    if (tid < CTOT) {
        const uint32_t wbase = smem_u32(&wns[0][0]);

        unsigned long long acc2[8];
        #pragma unroll
        for (int j = 0; j < 8; ++j) acc2[j] = 0ull;

        #pragma unroll
        for (int k = 0; k < KNN; ++k) {
            float f = feats[k][tid];
            unsigned long long ff;
            asm("mov.b64 %0, {%1, %1};" : "=l"(ff) : "f"(f));
            unsigned long long w0, w1, w2, w3, w4, w5, w6, w7;
            asm volatile("ld.shared.v2.u64 {%0, %1}, [%2];"
                         : "=l"(w0), "=l"(w1) : "r"(wbase + k * 64));
            asm volatile("ld.shared.v2.u64 {%0, %1}, [%2];"
                         : "=l"(w2), "=l"(w3) : "r"(wbase + k * 64 + 16));
            asm volatile("ld.shared.v2.u64 {%0, %1}, [%2];"
                         : "=l"(w4), "=l"(w5) : "r"(wbase + k * 64 + 32));
            asm volatile("ld.shared.v2.u64 {%0, %1}, [%2];"
                         : "=l"(w6), "=l"(w7) : "r"(wbase + k * 64 + 48));
            fma_f32x2(acc2[0], w0, ff);
            fma_f32x2(acc2[1], w1, ff);
            fma_f32x2(acc2[2], w2, ff);
            fma_f32x2(acc2[3], w3, ff);
            fma_f32x2(acc2[4], w4, ff);
            fma_f32x2(acc2[5], w5, ff);
            fma_f32x2(acc2[6], w6, ff);
            fma_f32x2(acc2[7], w7, ff);
        }

        float acc[16];
        #pragma unroll
        for (int j = 0; j < 8; ++j) {
            uint32_t lo, hi;
            asm("mov.b64 {%0, %1}, %2;" : "=r"(lo), "=r"(hi) : "l"(acc2[j]));
            acc[2 * j]     = __uint_as_float(lo);
            acc[2 * j + 1] = __uint_as_float(hi);
        }

        unsigned hh[8], ll[8];
        #pragma unroll
        for (int m = 0; m < 16; m += 2) {
            __nv_bfloat16 h0 = __float2bfloat16(acc[m]);
            __nv_bfloat16 h1 = __float2bfloat16(acc[m + 1]);
            __nv_bfloat16 l0 = __float2bfloat16(acc[m] - __bfloat162float(h0));
            __nv_bfloat16 l1 = __float2bfloat16(acc[m + 1] - __bfloat162float(h1));
            hh[m >> 1] = (unsigned)__bfloat16_as_ushort(h0) | ((unsigned)__bfloat16_as_ushort(h1) << 16);
            ll[m >> 1] = (unsigned)__bfloat16_as_ushort(l0) | ((unsigned)__bfloat16_as_ushort(l1) << 16);
        }
        uint4* dh = (uint4*)(g_Ph + (size_t)point * FDIMP + tid * 16);
        uint4* dl = (uint4*)(g_Pl + (size_t)point * FDIMP + tid * 16);
        dh[0] = make_uint4(hh[0], hh[1], hh[2], hh[3]);
        dh[1] = make_uint4(hh[4], hh[5], hh[6], hh[7]);
        dl[0] = make_uint4(ll[0], ll[1], ll[2], ll[3]);
        dl[1] = make_uint4(ll[4], ll[5], ll[6], ll[7]);
    }
    if (tid == 67) {   // zero K-pad [1072, 1088)
        uint4 z = make_uint4(0, 0, 0, 0);
        uint4* ph = (uint4*)(g_Ph + (size_t)point * FDIMP + FDIM);
        uint4* pl = (uint4*)(g_Pl + (size_t)point * FDIMP + FDIM);
        ph[0] = z; ph[1] = z; pl[0] = z; pl[1] = z;
    }
}

// ---------------------------------------------------------------------------
// Kernel 2: mma.sync bf16-split GEMM (R12 config, frozen).
// 625 blocks x (M=128, N=128), BK=32, 256 threads (8 warps, warp tile 32x64),
// 3-stage cp.async pipeline + XOR-swizzled 64B rows, 2 blocks/SM.
// Split-3: AhBh + AhBl + AlBh.
// ---------------------------------------------------------------------------
__global__ void __launch_bounds__(256, 2)
gemm_mma_kernel(const float* __restrict__ bias, float* __restrict__ out)
{
    extern __shared__ char dsm[];
    __shared__ float bias_s[COUT];

    const int tid  = threadIdx.x;
    const int lane = tid & 31;
    const int wid  = tid >> 5;
    const int wm   = wid & 3;            // 4 warps along M (32 rows each)
    const int wn   = wid >> 2;           // 2 warps along N (64 cols each)
    const size_t rowBase = (size_t)blockIdx.x * 128;
    const uint32_t tb = smem_u32(dsm);

    if (tid < COUT) bias_s[tid] = bias[tid];

    const char* srcs[4] = {
        (const char*)g_Ph + rowBase * ROWB,
        (const char*)g_Pl + rowBase * ROWB,
        (const char*)g_Wh,
        (const char*)g_Wl
    };

    auto load_chunk = [&](int chunk, int s) {
        const uint32_t st = tb + s * STAGE_SB;
        const size_t coff = (size_t)chunk * (BK * 2);   // 64 B along K
        #pragma unroll
        for (int i = 0; i < 8; ++i) {
            int j = tid + i * 256;          // 0..2047
            int tile = j >> 9;              // 0..3
            int idx  = j & 511;
            int row  = idx >> 2;            // 0..127
            int c    = idx & 3;             // logical 16B chunk in 64B row
            cpasync16(st + tile * TILE_SB + sw_off(row, c),
                      srcs[tile] + (size_t)row * ROWB + coff + c * 16);
        }
    };

    float acc[2][8][4];
    #pragma unroll
    for (int mt = 0; mt < 2; ++mt)
        #pragma unroll
        for (int nt = 0; nt < 8; ++nt)
            #pragma unroll
            for (int r = 0; r < 4; ++r) acc[mt][nt][r] = 0.f;

    const uint32_t a_row0 = (uint32_t)(wm * 32 + (lane & 15));
    const uint32_t a_c0   = (uint32_t)(lane >> 4);            // + k16*2
    const uint32_t b_row0 = (uint32_t)(wn * 64 + ((lane >> 4) << 3) + (lane & 7));
    const uint32_t b_c0   = (uint32_t)((lane >> 3) & 1);      // + k16*2

    load_chunk(0, 0); CP_COMMIT();
    load_chunk(1, 1); CP_COMMIT();

    for (int t = 0; t < NCH; ++t) {
        const int s = t % NSTG;
        if (t + 2 < NCH) load_chunk(t + 2, (t + 2) % NSTG);
        CP_COMMIT();          // one group per iteration (may be empty at tail)
        CP_WAIT2();           // chunk t resident
        __syncthreads();

        const uint32_t st = tb + s * STAGE_SB;

        #pragma unroll
        for (int k16 = 0; k16 < 2; ++k16) {
            uint32_t a_h[2][4], a_l[2][4], b_h[8][2], b_l[8][2];
            #pragma unroll
            for (int mt = 0; mt < 2; ++mt) {
                const uint32_t off = sw_off(a_row0 + mt * 16, a_c0 + k16 * 2);
                ldsm4(a_h[mt], st + off);
                ldsm4(a_l[mt], st + TILE_SB + off);
            }
            #pragma unroll
            for (int nt2 = 0; nt2 < 4; ++nt2) {
                const uint32_t off = sw_off(b_row0 + nt2 * 16, b_c0 + k16 * 2);
                uint32_t r[4];
                ldsm4(r, st + 2 * TILE_SB + off);
                b_h[nt2 * 2][0] = r[0]; b_h[nt2 * 2][1] = r[1];
                b_h[nt2 * 2 + 1][0] = r[2]; b_h[nt2 * 2 + 1][1] = r[3];
                ldsm4(r, st + 3 * TILE_SB + off);
                b_l[nt2 * 2][0] = r[0]; b_l[nt2 * 2][1] = r[1];
                b_l[nt2 * 2 + 1][0] = r[2]; b_l[nt2 * 2 + 1][1] = r[3];
            }
            #pragma unroll
            for (int mt = 0; mt < 2; ++mt)
                #pragma unroll
                for (int nt = 0; nt < 8; ++nt) {
                    mma_bf16(acc[mt][nt], a_h[mt], b_h[nt]);
                    mma_bf16(acc[mt][nt], a_h[mt], b_l[nt]);
                    mma_bf16(acc[mt][nt], a_l[mt], b_h[nt]);
                }
        }
        __syncthreads();
    }

    // epilogue: bias + store (float2 per fragment half-row)
    #pragma unroll
    for (int mt = 0; mt < 2; ++mt) {
        const size_t r0 = rowBase + (size_t)(wm * 32 + mt * 16 + (lane >> 2));
        #pragma unroll
        for (int nt = 0; nt < 8; ++nt) {
            const int col = wn * 64 + nt * 8 + (lane & 3) * 2;
            const float b0 = bias_s[col], b1 = bias_s[col + 1];
            *(float2*)(out + r0 * COUT + col) =
                make_float2(acc[mt][nt][0] + b0, acc[mt][nt][1] + b1);
            *(float2*)(out + (r0 + 8) * COUT + col) =
                make_float2(acc[mt][nt][2] + b0, acc[mt][nt][3] + b1);
        }
    }
}

// ---------------------------------------------------------------------------
// Launch
// ---------------------------------------------------------------------------
extern "C" void kernel_launch(void* const* d_in, const int* in_sizes, int n_in,
                              void* d_out, int out_size)
{
    const float* in_feat = (const float*)d_in[0];
    const void*  ninds   = d_in[1];
    const float* wn      = (const float*)d_in[5];
    const float* addf    = (const float*)d_in[6];
    const float* W       = (const float*)d_in[7];
    const float* bias    = (const float*)d_in[8];
    float*       out     = (float*)d_out;

    cudaFuncSetAttribute(gemm_mma_kernel,
                         cudaFuncAttributeMaxDynamicSharedMemorySize, SMEM_DYN);

    detect_kernel<<<1, 1>>>(ninds);
    wconv_kernel<<<(COUT * FDIMP + 255) / 256, 256>>>(W);
    pconv_kernel<<<TOTPTS, 128>>>(in_feat, ninds, wn, addf);
    gemm_mma_kernel<<<TOTPTS / 128, 256, SMEM_DYN>>>(bias, out);
}